// round 3
// baseline (speedup 1.0000x reference)
#include <cuda_runtime.h>
#include <cuda_fp16.h>
#include <stdint.h>
#include <math.h>

#define DEVFN __device__ __forceinline__

static constexpr int NNODE = 4096, DIM = 128;
static constexpr int NU = 100000, NR = 32, NA = 5000;

// ---- device scratch (no allocs allowed) ----
__device__ __align__(16) __half g_u2e_h [NU * DIM];
__device__ __align__(16) __half g_ua2e_h[NA * DIM];
__device__ __align__(16) float  g_R12T  [2 * NR * 256];   // rows 0-31: r-slot0 (incl b1); 32-63: r-slot1
__device__ __align__(16) float  g_selfA1[NNODE * DIM];
__device__ __align__(16) __half g_B1    [2 * 128 * 320];  // BT for G1, two n-halves: [h][n][k]
__device__ __align__(16) __half g_B2    [128 * 256];      // BT2[n][k] = W2[k][n]
__device__ __align__(16) __half g_B3    [128 * 128];      // A1 top: [n][k] = A1[k][n]
__device__ __align__(16) __half g_B4    [128 * 128];      // A2:     [n][k] = A2[k][n]

// ---- smem layout (bytes) ----
static constexpr uint32_t OFF_B2S = 0, OFF_AB2 = 512, OFF_A3 = 1024, OFF_SA = 1536,
    OFF_LG = 2560, OFF_LGP = 3072, OFF_WGT = 4096, OFF_OUT = 4608, OFF_AB3 = 5632,
    OFF_XB = 6144, OFF_WB = 6144 + 84480;
static constexpr uint32_t SMEM_BYTES = OFF_WB + 84480;    // 175104
static constexpr int XS = 328;                            // X tile stride in halfs (pad 8)

// ---- PTX helpers ----
DEVFN uint32_t smem_u32(const void* p) {
    uint32_t a;
    asm("{ .reg .u64 t; cvta.to.shared.u64 t, %1; cvt.u32.u64 %0, t; }" : "=r"(a) : "l"(p));
    return a;
}
DEVFN void ldm4(uint32_t* r, uint32_t a) {
    asm volatile("ldmatrix.sync.aligned.m8n8.x4.shared.b16 {%0,%1,%2,%3}, [%4];"
                 : "=r"(r[0]), "=r"(r[1]), "=r"(r[2]), "=r"(r[3]) : "r"(a));
}
DEVFN void ldm2(uint32_t& r0, uint32_t& r1, uint32_t a) {
    asm volatile("ldmatrix.sync.aligned.m8n8.x2.shared.b16 {%0,%1}, [%2];"
                 : "=r"(r0), "=r"(r1) : "r"(a));
}
DEVFN void mma16816(float* c, const uint32_t* a, uint32_t b0, uint32_t b1) {
    asm volatile("mma.sync.aligned.m16n8k16.row.col.f32.f16.f16.f32 "
                 "{%0,%1,%2,%3}, {%4,%5,%6,%7}, {%8,%9}, {%0,%1,%2,%3};"
                 : "+f"(c[0]), "+f"(c[1]), "+f"(c[2]), "+f"(c[3])
                 : "r"(a[0]), "r"(a[1]), "r"(a[2]), "r"(a[3]), "r"(b0), "r"(b1));
}

// GEMM: C[128x128] += A[128xK](smem, stride XS) * BT[128xK](smem, stride K+8)
// warp (mg=wid>>1 owns 32 rows, ng=wid&1 owns 64 cols); acc[mf][nt][e]
template<int K>
DEVFN void gemm_tile(uint32_t aXbase, uint32_t aWbase, float (&acc)[2][8][4],
                     int lane, int mg, int ng) {
    constexpr int WS = K + 8, KS = K / 16;
    uint32_t aA = aXbase + (uint32_t)((mg * 32 + ((lane >> 3) & 1) * 8 + (lane & 7)) * XS
                                      + ((lane >> 3) >> 1) * 8) * 2;
    uint32_t aB = aWbase + (uint32_t)((ng * 64 + (lane & 7)) * WS + ((lane >> 3) & 1) * 8) * 2;
    #pragma unroll
    for (int m = 0; m < 2; m++)
        #pragma unroll
        for (int n = 0; n < 8; n++)
            #pragma unroll
            for (int e = 0; e < 4; e++) acc[m][n][e] = 0.f;
    #pragma unroll 1
    for (int ks = 0; ks < KS; ks++) {
        uint32_t af[2][4];
        ldm4(af[0], aA + ks * 32);
        ldm4(af[1], aA + 16 * XS * 2 + ks * 32);
        #pragma unroll
        for (int nt = 0; nt < 8; nt++) {
            uint32_t b0, b1;
            ldm2(b0, b1, aB + nt * (8 * WS * 2) + ks * 32);
            mma16816(acc[0][nt], af[0], b0, b1);
            mma16816(acc[1][nt], af[1], b0, b1);
        }
    }
}

template<int K>
DEVFN void copyB(char* WB, const __half* src, int tid) {
    constexpr int RQ = K / 8;   // uint4 per row
    const uint4* s = (const uint4*)src;
    #pragma unroll 1
    for (int i = tid; i < 128 * RQ; i += 256) {
        int n = i / RQ, j = i % RQ;
        *(uint4*)(WB + (n * (K + 8) + j * 8) * 2) = s[i];
    }
}

// ================= prepass =================
__global__ void k_convert(const float* __restrict__ u2e, const float* __restrict__ ua2e) {
    int st = gridDim.x * blockDim.x, t0 = blockIdx.x * blockDim.x + threadIdx.x;
    const float4* s1 = (const float4*)u2e;  __half2* d1 = (__half2*)g_u2e_h;
    for (int i = t0; i < NU * DIM / 4; i += st) {
        float4 v = s1[i];
        d1[2 * i] = __floats2half2_rn(v.x, v.y); d1[2 * i + 1] = __floats2half2_rn(v.z, v.w);
    }
    const float4* s2 = (const float4*)ua2e;  __half2* d2 = (__half2*)g_ua2e_h;
    for (int i = t0; i < NA * DIM / 4; i += st) {
        float4 v = s2[i];
        d2[2 * i] = __floats2half2_rn(v.x, v.y); d2[2 * i + 1] = __floats2half2_rn(v.z, v.w);
    }
}

__global__ void k_r12(const float* __restrict__ r2e, const float* __restrict__ W1,
                      const float* __restrict__ b1) {
    __shared__ float rr[128];
    int b = blockIdx.x, t = b >> 5, i = b & 31, c = threadIdx.x;   // 64 x 256
    if (c < 128) rr[c] = r2e[i * 128 + c];
    __syncthreads();
    float acc = (t == 0) ? b1[c] : 0.f;
    #pragma unroll 4
    for (int k = 0; k < 128; k++) acc += rr[k] * W1[(t * 128 + k) * 256 + c];
    g_R12T[(t * 32 + i) * 256 + c] = acc;
}

__global__ void k_selfA1(const int* __restrict__ nodes, const float* __restrict__ u2e,
                         const float* __restrict__ A1, const float* __restrict__ ab1) {
    extern __shared__ float As[];      // A1 bottom half [128k][128c]
    __shared__ float se[128];
    int tid = threadIdx.x;             // 512 blocks x 128 thr
    for (int i = tid; i < 16384; i += 128) As[i] = A1[16384 + i];
    __syncthreads();
    for (int s = 0; s < 8; s++) {
        int n = blockIdx.x * 8 + s, nd = nodes[n];
        se[tid] = u2e[(size_t)nd * 128 + tid];
        __syncthreads();
        float acc = ab1[tid];
        #pragma unroll 8
        for (int k = 0; k < 128; k++) acc += se[k] * As[k * 128 + tid];
        g_selfA1[n * 128 + tid] = acc;
        __syncthreads();
    }
}

__global__ void k_pack(const float* __restrict__ W1, const float* __restrict__ W2,
                       const float* __restrict__ A1, const float* __restrict__ A2) {
    int id = blockIdx.x * 256 + threadIdx.x;   // 576 x 256 = 147456
    if (id < 81920) {                          // G1: [h][n][k], k<256 -> W1 rows 256+k
        int h = id / 40960, e = id % 40960, n = e / 320, k = e % 320;
        float v;
        if (k < 256)      v = W1[(256 + k) * 256 + h * 128 + n];
        else if (k < 288) v = g_R12T[(k - 256) * 256 + h * 128 + n];
        else              v = g_R12T[(32 + (k - 288)) * 256 + h * 128 + n];
        g_B1[h * 40960 + n * 320 + k] = __float2half_rn(v);
    } else if (id < 114688) {
        int e = id - 81920, n = e / 256, k = e % 256;
        g_B2[n * 256 + k] = __float2half_rn(W2[k * 128 + n]);
    } else if (id < 131072) {
        int e = id - 114688, n = e / 128, k = e % 128;
        g_B3[n * 128 + k] = __float2half_rn(A1[k * 128 + n]);
    } else {
        int e = id - 131072, n = e / 128, k = e % 128;
        g_B4[n * 128 + k] = __float2half_rn(A2[k * 128 + n]);
    }
}

// ================= main fused kernel =================
__global__ void __launch_bounds__(256, 1)
k_main(const int* __restrict__ prel, const int* __restrict__ pnbr,
       const int* __restrict__ attrs,
       const float* __restrict__ b2, const float* __restrict__ ab2,
       const float* __restrict__ A3, const float* __restrict__ ab3,
       float* __restrict__ out) {
    extern __shared__ char sm[];
    const uint32_t sb = smem_u32(sm);
    const int tid = threadIdx.x, wid = tid >> 5, lane = tid & 31;
    const int mg = wid >> 1, ng = wid & 1;
    const int tile = blockIdx.x;

    float* b2s  = (float*)(sm + OFF_B2S);
    float* ab2s = (float*)(sm + OFF_AB2);
    float* A3s  = (float*)(sm + OFF_A3);
    float* SA   = (float*)(sm + OFF_SA);
    float* LG   = (float*)(sm + OFF_LG);
    float* LGP  = (float*)(sm + OFF_LGP);
    float* wgs  = (float*)(sm + OFF_WGT);
    float* OUTa = (float*)(sm + OFF_OUT);
    char*  XB   = sm + OFF_XB;
    char*  WB   = sm + OFF_WB;
    const uint32_t aXB = sb + OFF_XB, aWB = sb + OFF_WB;

    if (tid < 128) { b2s[tid] = b2[tid]; ab2s[tid] = ab2[tid]; A3s[tid] = A3[tid]; }
    if (tid == 0) *(float*)(sm + OFF_AB3) = ab3[0];
    SA[tid] = g_selfA1[(size_t)tile * 256 + tid];
    OUTa[tid] = 0.f;

    // ---- build X = [ne(128) | ae(128) | onehot r0(32) | onehot r1(32)] ----
    {
        int row = tid >> 1, side = tid & 1, p = tile * 128 + row;
        char* XR = XB + row * (XS * 2);
        if (side == 0) {
            int nbr = pnbr[p];
            const uint4* s = (const uint4*)(g_u2e_h + (size_t)nbr * 128);
            #pragma unroll
            for (int j = 0; j < 16; j++) ((uint4*)XR)[j] = s[j];
            #pragma unroll
            for (int j = 0; j < 8; j++) ((uint4*)(XR + 512))[j] = make_uint4(0, 0, 0, 0);
            int r0 = prel[p * 2], r1 = prel[p * 2 + 1];
            *(__half*)(XR + (256 + r0) * 2) = __ushort_as_half((unsigned short)0x3C00);
            *(__half*)(XR + (288 + r1) * 2) = __ushort_as_half((unsigned short)0x3C00);
        } else {
            int at[8];
            const int4* ap = (const int4*)(attrs + (size_t)p * 8);
            int4 a0 = ap[0], a1 = ap[1];
            at[0]=a0.x; at[1]=a0.y; at[2]=a0.z; at[3]=a0.w;
            at[4]=a1.x; at[5]=a1.y; at[6]=a1.z; at[7]=a1.w;
            #pragma unroll 1
            for (int hh = 0; hh < 2; hh++) {
                float2 acc[32];
                #pragma unroll
                for (int i = 0; i < 32; i++) { acc[i].x = 0.f; acc[i].y = 0.f; }
                #pragma unroll 1
                for (int a = 0; a < 8; a++) {
                    const __half2* q = (const __half2*)(g_ua2e_h + (size_t)at[a] * 128 + hh * 64);
                    #pragma unroll
                    for (int i = 0; i < 32; i++) {
                        float2 f = __half22float2(q[i]);
                        acc[i].x += f.x; acc[i].y += f.y;
                    }
                }
                #pragma unroll
                for (int i = 0; i < 32; i++)
                    *(__half2*)(XR + (128 + hh * 64 + 2 * i) * 2) =
                        __floats2half2_rn(acc[i].x, acc[i].y);
            }
        }
    }
    copyB<320>(WB, g_B1, tid);
    __syncthreads();

    float acc1[2][8][4], acc2[2][8][4];

    // G1a: X @ B1[half0] -> acc1 (h1 cols 0-127)
    gemm_tile<320>(aXB, aWB, acc1, lane, mg, ng);
    __syncthreads();
    copyB<320>(WB, g_B1 + 40960, tid);
    __syncthreads();
    // G1b: X @ B1[half1] -> acc2 (h1 cols 128-255)
    gemm_tile<320>(aXB, aWB, acc2, lane, mg, ng);
    __syncthreads();

    // epilogue1: h1 = relu(acc1|acc2) -> fp16 XB cols 0-255 (overwrites X)
    {
        #pragma unroll
        for (int mf = 0; mf < 2; mf++) {
            int row = mg * 32 + mf * 16 + (lane >> 2);
            #pragma unroll
            for (int nt = 0; nt < 8; nt++) {
                int col = ng * 64 + nt * 8 + (lane & 3) * 2;
                *(__half2*)(XB + (row * XS + col) * 2) =
                    __floats2half2_rn(fmaxf(acc1[mf][nt][0], 0.f), fmaxf(acc1[mf][nt][1], 0.f));
                *(__half2*)(XB + ((row + 8) * XS + col) * 2) =
                    __floats2half2_rn(fmaxf(acc1[mf][nt][2], 0.f), fmaxf(acc1[mf][nt][3], 0.f));
                *(__half2*)(XB + (row * XS + col + 128) * 2) =
                    __floats2half2_rn(fmaxf(acc2[mf][nt][0], 0.f), fmaxf(acc2[mf][nt][1], 0.f));
                *(__half2*)(XB + ((row + 8) * XS + col + 128) * 2) =
                    __floats2half2_rn(fmaxf(acc2[mf][nt][2], 0.f), fmaxf(acc2[mf][nt][3], 0.f));
            }
        }
    }
    copyB<256>(WB, g_B2, tid);
    __syncthreads();
    // G2: h1 @ B2 -> acc2 = h pre-bias (fp32, kept in regs)
    gemm_tile<256>(aXB, aWB, acc2, lane, mg, ng);
    __syncthreads();

    // epilogue2: h = relu(acc2 + b2) ; keep fp32 in acc2, write fp16 to XB cols 0-127
    {
        #pragma unroll
        for (int mf = 0; mf < 2; mf++) {
            int row = mg * 32 + mf * 16 + (lane >> 2);
            #pragma unroll
            for (int nt = 0; nt < 8; nt++) {
                int col = ng * 64 + nt * 8 + (lane & 3) * 2;
                float v0 = fmaxf(acc2[mf][nt][0] + b2s[col],     0.f);
                float v1 = fmaxf(acc2[mf][nt][1] + b2s[col + 1], 0.f);
                float v2 = fmaxf(acc2[mf][nt][2] + b2s[col],     0.f);
                float v3 = fmaxf(acc2[mf][nt][3] + b2s[col + 1], 0.f);
                acc2[mf][nt][0] = v0; acc2[mf][nt][1] = v1;
                acc2[mf][nt][2] = v2; acc2[mf][nt][3] = v3;
                *(__half2*)(XB + (row * XS + col) * 2)       = __floats2half2_rn(v0, v1);
                *(__half2*)(XB + ((row + 8) * XS + col) * 2) = __floats2half2_rn(v2, v3);
            }
        }
    }
    copyB<128>(WB, g_B3, tid);
    __syncthreads();
    // G3: h @ A1top -> acc1
    gemm_tile<128>(aXB, aWB, acc1, lane, mg, ng);
    __syncthreads();

    // epilogue3: a1 = relu(acc1 + selfA1[node]) -> fp16 XB cols 128-255
    {
        int node = mg >> 1;
        #pragma unroll
        for (int mf = 0; mf < 2; mf++) {
            int row = mg * 32 + mf * 16 + (lane >> 2);
            #pragma unroll
            for (int nt = 0; nt < 8; nt++) {
                int col = ng * 64 + nt * 8 + (lane & 3) * 2;
                float s0 = SA[node * 128 + col], s1 = SA[node * 128 + col + 1];
                *(__half2*)(XB + (row * XS + col + 128) * 2) =
                    __floats2half2_rn(fmaxf(acc1[mf][nt][0] + s0, 0.f),
                                      fmaxf(acc1[mf][nt][1] + s1, 0.f));
                *(__half2*)(XB + ((row + 8) * XS + col + 128) * 2) =
                    __floats2half2_rn(fmaxf(acc1[mf][nt][2] + s0, 0.f),
                                      fmaxf(acc1[mf][nt][3] + s1, 0.f));
            }
        }
    }
    copyB<128>(WB, g_B4, tid);
    __syncthreads();
    // G4: a1 @ A2 -> acc1  (A base = XB + 128 cols)
    gemm_tile<128>(aXB + 256, aWB, acc1, lane, mg, ng);
    __syncthreads();

    // epilogue4: a2 = relu(acc1 + ab2); logits partial = sum a2 * A3
    {
        float lp[4] = {0.f, 0.f, 0.f, 0.f};
        #pragma unroll
        for (int mf = 0; mf < 2; mf++)
            #pragma unroll
            for (int nt = 0; nt < 8; nt++) {
                int col = ng * 64 + nt * 8 + (lane & 3) * 2;
                float a30 = A3s[col], a31 = A3s[col + 1];
                float c0 = ab2s[col], c1 = ab2s[col + 1];
                lp[mf * 2 + 0] += fmaxf(acc1[mf][nt][0] + c0, 0.f) * a30
                                + fmaxf(acc1[mf][nt][1] + c1, 0.f) * a31;
                lp[mf * 2 + 1] += fmaxf(acc1[mf][nt][2] + c0, 0.f) * a30
                                + fmaxf(acc1[mf][nt][3] + c1, 0.f) * a31;
            }
        #pragma unroll
        for (int j = 0; j < 4; j++) {
            lp[j] += __shfl_xor_sync(0xffffffffu, lp[j], 1);
            lp[j] += __shfl_xor_sync(0xffffffffu, lp[j], 2);
        }
        if ((lane & 3) == 0) {
            int rbase = mg * 32 + (lane >> 2);
            #pragma unroll
            for (int j = 0; j < 4; j++)
                LGP[ng * 128 + rbase + j * 8] = lp[j];
        }
    }
    __syncthreads();
    if (tid < 128) LG[tid] = LGP[tid] + LGP[128 + tid] + *(float*)(sm + OFF_AB3);
    __syncthreads();
    if (wid < 2) {   // softmax per node over its 64 logits
        float a = LG[wid * 64 + lane], b = LG[wid * 64 + 32 + lane];
        float m = fmaxf(a, b);
        #pragma unroll
        for (int o = 16; o; o >>= 1) m = fmaxf(m, __shfl_xor_sync(0xffffffffu, m, o));
        float e1 = __expf(a - m), e2 = __expf(b - m), s = e1 + e2;
        #pragma unroll
        for (int o = 16; o; o >>= 1) s += __shfl_xor_sync(0xffffffffu, s, o);
        wgs[wid * 64 + lane] = e1 / s; wgs[wid * 64 + 32 + lane] = e2 / s;
    }
    __syncthreads();

    // weighted reduce: out[node][col] = sum_r wgs[r] * h[r][col]  (h fp32 in acc2)
    {
        float p[16];
        #pragma unroll
        for (int i = 0; i < 16; i++) p[i] = 0.f;
        #pragma unroll
        for (int mf = 0; mf < 2; mf++) {
            int r0 = mg * 32 + mf * 16 + (lane >> 2);
            float w0 = wgs[r0], w1 = wgs[r0 + 8];
            #pragma unroll
            for (int nt = 0; nt < 8; nt++) {
                p[nt * 2 + 0] += w0 * acc2[mf][nt][0] + w1 * acc2[mf][nt][2];
                p[nt * 2 + 1] += w0 * acc2[mf][nt][1] + w1 * acc2[mf][nt][3];
            }
        }
        #pragma unroll
        for (int i = 0; i < 16; i++) {
            p[i] += __shfl_xor_sync(0xffffffffu, p[i], 4);
            p[i] += __shfl_xor_sync(0xffffffffu, p[i], 8);
            p[i] += __shfl_xor_sync(0xffffffffu, p[i], 16);
        }
        if (lane < 4) {
            int node = mg >> 1;
            #pragma unroll
            for (int i = 0; i < 16; i++) {
                int col = ng * 64 + (i >> 1) * 8 + lane * 2 + (i & 1);
                atomicAdd(&OUTa[node * 128 + col], p[i]);
            }
        }
    }
    __syncthreads();
    out[(size_t)tile * 256 + tid] = OUTa[tid];
}

// ================= launch =================
extern "C" void kernel_launch(void* const* d_in, const int* in_sizes, int n_in,
                              void* d_out, int out_size) {
    const int*   nodes = (const int*)  d_in[0];
    const int*   prel  = (const int*)  d_in[1];
    const int*   pnbr  = (const int*)  d_in[2];
    const int*   attrs = (const int*)  d_in[3];
    const float* u2e   = (const float*)d_in[4];
    const float* r2e   = (const float*)d_in[5];
    const float* ua2e  = (const float*)d_in[6];
    const float* W1    = (const float*)d_in[7];
    const float* b1    = (const float*)d_in[8];
    const float* W2    = (const float*)d_in[9];
    const float* b2    = (const float*)d_in[10];
    const float* A1    = (const float*)d_in[11];
    const float* ab1   = (const float*)d_in[12];
    const float* A2    = (const float*)d_in[13];
    const float* ab2   = (const float*)d_in[14];
    const float* A3    = (const float*)d_in[15];
    const float* ab3   = (const float*)d_in[16];
    float* out = (float*)d_out;

    cudaFuncSetAttribute(k_selfA1, cudaFuncAttributeMaxDynamicSharedMemorySize, 65536);
    cudaFuncSetAttribute(k_main,   cudaFuncAttributeMaxDynamicSharedMemorySize, (int)SMEM_BYTES);

    k_convert<<<512, 256>>>(u2e, ua2e);
    k_r12<<<64, 256>>>(r2e, W1, b1);
    k_selfA1<<<512, 128, 65536>>>(nodes, u2e, A1, ab1);
    k_pack<<<576, 256>>>(W1, W2, A1, A2);
    k_main<<<2048, 256, SMEM_BYTES>>>(prel, pnbr, attrs, b2, ab2, A3, ab3, out);
}

// round 4
// speedup vs baseline: 1.3851x; 1.3851x over previous
#include <cuda_runtime.h>
#include <cuda_fp16.h>
#include <stdint.h>
#include <math.h>

#define DEVFN __device__ __forceinline__

static constexpr int NNODE = 4096, DIM = 128;
static constexpr int NU = 100000, NR = 32, NA = 5000;

// ---- device scratch (no allocs allowed) ----
__device__ __align__(16) __half g_u2e_h [NU * DIM];
__device__ __align__(16) __half g_ua2e_h[NA * DIM];
__device__ __align__(16) float  g_R12T  [2 * NR * 256];
__device__ __align__(16) float  g_selfA1[NNODE * DIM];
// B operands in MMA-fragment order: uint2(b0,b1) indexed [ks][nb][lane]
__device__ __align__(16) uint2  g_FG1[2 * 20 * 16 * 32];  // G1 two n-halves, K=320
__device__ __align__(16) uint2  g_FG2[16 * 16 * 32];      // G2 K=256
__device__ __align__(16) uint2  g_FG3[8 * 16 * 32];       // G3 K=128
__device__ __align__(16) uint2  g_FG4[8 * 16 * 32];       // G4 K=128

// ---- smem layout (bytes) ----
static constexpr uint32_t OFF_B2S = 0, OFF_AB2 = 512, OFF_A3 = 1024, OFF_SA = 1536,
    OFF_LG = 2560, OFF_LGP = 3072, OFF_WGT = 5120, OFF_OUT = 5632, OFF_AB3 = 6656,
    OFF_XB = 6912;
static constexpr int XS = 328;                        // X stride (halfs)
static constexpr uint32_t SMEM_BYTES = OFF_XB + 128 * XS * 2;   // 90880

// ---- PTX helpers ----
DEVFN uint32_t smem_u32(const void* p) {
    uint32_t a;
    asm("{ .reg .u64 t; cvta.to.shared.u64 t, %1; cvt.u32.u64 %0, t; }" : "=r"(a) : "l"(p));
    return a;
}
DEVFN void ldm4(uint32_t* r, uint32_t a) {
    asm volatile("ldmatrix.sync.aligned.m8n8.x4.shared.b16 {%0,%1,%2,%3}, [%4];"
                 : "=r"(r[0]), "=r"(r[1]), "=r"(r[2]), "=r"(r[3]) : "r"(a));
}
DEVFN void mma16816(float* c, const uint32_t* a, uint32_t b0, uint32_t b1) {
    asm volatile("mma.sync.aligned.m16n8k16.row.col.f32.f16.f16.f32 "
                 "{%0,%1,%2,%3}, {%4,%5,%6,%7}, {%8,%9}, {%0,%1,%2,%3};"
                 : "+f"(c[0]), "+f"(c[1]), "+f"(c[2]), "+f"(c[3])
                 : "r"(a[0]), "r"(a[1]), "r"(a[2]), "r"(a[3]), "r"(b0), "r"(b1));
}

// GEMM: C[128x128] += A[128xK](smem, stride XS) * B(frag array in gmem)
// warp grid 4x4: mg owns 32 rows, ng owns 32 cols; acc[mf][nt][e]
template<int K>
DEVFN void gemm_tile(uint32_t aXbase, const uint2* __restrict__ F,
                     float (&acc)[2][4][4], int lane, int mg, int ng) {
    constexpr int KS = K / 16;
    uint32_t aA = aXbase + (uint32_t)((mg * 32 + ((lane >> 3) & 1) * 8 + (lane & 7)) * XS
                                      + (lane >> 4) * 8) * 2;
    const uint2* Fw = F + (ng * 4) * 32 + lane;
    #pragma unroll
    for (int m = 0; m < 2; m++)
        #pragma unroll
        for (int n = 0; n < 4; n++)
            #pragma unroll
            for (int e = 0; e < 4; e++) acc[m][n][e] = 0.f;
    #pragma unroll 1
    for (int ks = 0; ks < KS; ks++) {
        uint2 bf[4];
        #pragma unroll
        for (int nt = 0; nt < 4; nt++) bf[nt] = __ldg(Fw + (ks * 16 + nt) * 32);
        uint32_t a0[4], a1[4];
        ldm4(a0, aA + ks * 32);
        ldm4(a1, aA + 16 * XS * 2 + ks * 32);
        #pragma unroll
        for (int nt = 0; nt < 4; nt++) {
            mma16816(acc[0][nt], a0, bf[nt].x, bf[nt].y);
            mma16816(acc[1][nt], a1, bf[nt].x, bf[nt].y);
        }
    }
}

// ================= prepass =================
__global__ void k_convert(const float* __restrict__ u2e, const float* __restrict__ ua2e) {
    int st = gridDim.x * blockDim.x, t0 = blockIdx.x * blockDim.x + threadIdx.x;
    const float4* s1 = (const float4*)u2e;  __half2* d1 = (__half2*)g_u2e_h;
    for (int i = t0; i < NU * DIM / 4; i += st) {
        float4 v = s1[i];
        d1[2 * i] = __floats2half2_rn(v.x, v.y); d1[2 * i + 1] = __floats2half2_rn(v.z, v.w);
    }
    const float4* s2 = (const float4*)ua2e;  __half2* d2 = (__half2*)g_ua2e_h;
    for (int i = t0; i < NA * DIM / 4; i += st) {
        float4 v = s2[i];
        d2[2 * i] = __floats2half2_rn(v.x, v.y); d2[2 * i + 1] = __floats2half2_rn(v.z, v.w);
    }
}

__global__ void k_r12(const float* __restrict__ r2e, const float* __restrict__ W1,
                      const float* __restrict__ b1) {
    __shared__ float rr[128];
    int b = blockIdx.x, t = b >> 5, i = b & 31, c = threadIdx.x;   // 64 x 256
    if (c < 128) rr[c] = r2e[i * 128 + c];
    __syncthreads();
    float acc = (t == 0) ? b1[c] : 0.f;
    #pragma unroll 4
    for (int k = 0; k < 128; k++) acc += rr[k] * W1[(t * 128 + k) * 256 + c];
    g_R12T[(t * 32 + i) * 256 + c] = acc;
}

__global__ void k_selfA1(const int* __restrict__ nodes, const float* __restrict__ u2e,
                         const float* __restrict__ A1, const float* __restrict__ ab1) {
    extern __shared__ float As[];      // A1 bottom half [128k][128c]
    __shared__ float se[128];
    int tid = threadIdx.x;             // 512 blocks x 128 thr
    for (int i = tid; i < 16384; i += 128) As[i] = A1[16384 + i];
    __syncthreads();
    for (int s = 0; s < 8; s++) {
        int n = blockIdx.x * 8 + s, nd = nodes[n];
        se[tid] = u2e[(size_t)nd * 128 + tid];
        __syncthreads();
        float acc = ab1[tid];
        #pragma unroll 8
        for (int k = 0; k < 128; k++) acc += se[k] * As[k * 128 + tid];
        g_selfA1[n * 128 + tid] = acc;
        __syncthreads();
    }
}

DEVFN uint32_t pack2(float a, float b) {
    __half2 h = __floats2half2_rn(a, b);
    return *(uint32_t*)&h;
}

// pack B operands into MMA fragment order
__global__ void k_pack(const float* __restrict__ W1, const float* __restrict__ W2,
                       const float* __restrict__ A1, const float* __restrict__ A2) {
    int id = blockIdx.x * 256 + threadIdx.x;   // 144 x 256 = 36864
    int table, rem, h = 0;
    if (id < 20480)      { table = 1; h = id / 10240; rem = id % 10240; }
    else if (id < 28672) { table = 2; rem = id - 20480; }
    else if (id < 32768) { table = 3; rem = id - 28672; }
    else                 { table = 4; rem = id - 32768; }
    int lane = rem & 31, nb = (rem >> 5) & 15, ks = rem >> 9;
    int n = nb * 8 + (lane >> 2), k0 = ks * 16 + (lane & 3) * 2;

    float v[4];
    #pragma unroll
    for (int j = 0; j < 4; j++) {
        int k = k0 + (j >> 1) * 8 + (j & 1);
        float val;
        if (table == 1) {
            int ngl = h * 128 + n;
            if (k < 256)      val = W1[(256 + k) * 256 + ngl];
            else if (k < 288) val = g_R12T[(k - 256) * 256 + ngl];
            else              val = g_R12T[(32 + (k - 288)) * 256 + ngl];
        } else if (table == 2) val = W2[k * 128 + n];
        else if (table == 3)   val = A1[k * 128 + n];
        else                   val = A2[k * 128 + n];
        v[j] = val;
    }
    uint2 fr = make_uint2(pack2(v[0], v[1]), pack2(v[2], v[3]));
    if (table == 1)      g_FG1[h * 10240 + rem] = fr;
    else if (table == 2) g_FG2[rem] = fr;
    else if (table == 3) g_FG3[rem] = fr;
    else                 g_FG4[rem] = fr;
}

// ================= main fused kernel =================
__global__ void __launch_bounds__(512, 1)
k_main(const int* __restrict__ prel, const int* __restrict__ pnbr,
       const int* __restrict__ attrs,
       const float* __restrict__ b2, const float* __restrict__ ab2,
       const float* __restrict__ A3, const float* __restrict__ ab3,
       float* __restrict__ out) {
    extern __shared__ char sm[];
    const uint32_t sb = smem_u32(sm);
    const int tid = threadIdx.x, wid = tid >> 5, lane = tid & 31;
    const int mg = wid >> 2, ng = wid & 3;
    const int tile = blockIdx.x;

    float* b2s  = (float*)(sm + OFF_B2S);
    float* ab2s = (float*)(sm + OFF_AB2);
    float* A3s  = (float*)(sm + OFF_A3);
    float* SA   = (float*)(sm + OFF_SA);
    float* LG   = (float*)(sm + OFF_LG);
    float* LGP  = (float*)(sm + OFF_LGP);
    float* wgs  = (float*)(sm + OFF_WGT);
    float* OUTa = (float*)(sm + OFF_OUT);
    char*  XB   = sm + OFF_XB;
    const uint32_t aXB = sb + OFF_XB;

    if (tid < 128) { b2s[tid] = b2[tid]; ab2s[tid] = ab2[tid]; A3s[tid] = A3[tid]; }
    if (tid == 0) *(float*)(sm + OFF_AB3) = ab3[0];
    if (tid < 256) { SA[tid] = g_selfA1[(size_t)tile * 256 + tid]; OUTa[tid] = 0.f; }

    // ---- build X = [ne(128) | ae(128) | onehot r0(32) | onehot r1(32)], 4 thr/row ----
    {
        int row = tid >> 2, q = tid & 3, p = tile * 128 + row;
        char* XR = XB + row * (XS * 2);
        int nbr = pnbr[p];
        // ne cols q*32..+31
        const uint4* s = (const uint4*)(g_u2e_h + (size_t)nbr * 128 + q * 32);
        #pragma unroll
        for (int j = 0; j < 4; j++) ((uint4*)XR)[q * 4 + j] = s[j];
        // one-hot region (cols 256-319): q==0 zeros + sets
        if (q == 0) {
            #pragma unroll
            for (int j = 0; j < 8; j++) ((uint4*)(XR + 512))[j] = make_uint4(0, 0, 0, 0);
        }
        // ae cols 128 + q*32 .. +31
        int at[8];
        const int4* ap = (const int4*)(attrs + (size_t)p * 8);
        int4 a0v = ap[0], a1v = ap[1];
        at[0]=a0v.x; at[1]=a0v.y; at[2]=a0v.z; at[3]=a0v.w;
        at[4]=a1v.x; at[5]=a1v.y; at[6]=a1v.z; at[7]=a1v.w;
        float2 acc[16];
        #pragma unroll
        for (int i = 0; i < 16; i++) { acc[i].x = 0.f; acc[i].y = 0.f; }
        #pragma unroll 1
        for (int a = 0; a < 8; a++) {
            const __half2* qp = (const __half2*)(g_ua2e_h + (size_t)at[a] * 128 + q * 32);
            #pragma unroll
            for (int i = 0; i < 16; i++) {
                float2 f = __half22float2(qp[i]);
                acc[i].x += f.x; acc[i].y += f.y;
            }
        }
        #pragma unroll
        for (int i = 0; i < 16; i++)
            *(__half2*)(XR + (128 + q * 32 + 2 * i) * 2) = __floats2half2_rn(acc[i].x, acc[i].y);
        if (q == 0) {
            int r0 = prel[p * 2], r1 = prel[p * 2 + 1];
            *(__half*)(XR + (256 + r0) * 2) = __ushort_as_half((unsigned short)0x3C00);
            *(__half*)(XR + (288 + r1) * 2) = __ushort_as_half((unsigned short)0x3C00);
        }
    }
    __syncthreads();

    float acc1[2][4][4], acc2[2][4][4];

    // G1a/G1b: X @ W1' -> h1 cols 0-127 (acc1), 128-255 (acc2)
    gemm_tile<320>(aXB, g_FG1,         acc1, lane, mg, ng);
    gemm_tile<320>(aXB, g_FG1 + 10240, acc2, lane, mg, ng);
    __syncthreads();

    // epilogue1: h1 = relu -> fp16 XB cols 0-255 (overwrites X)
    #pragma unroll
    for (int mf = 0; mf < 2; mf++) {
        int row = mg * 32 + mf * 16 + (lane >> 2);
        #pragma unroll
        for (int nt = 0; nt < 4; nt++) {
            int col = ng * 32 + nt * 8 + (lane & 3) * 2;
            *(__half2*)(XB + (row * XS + col) * 2) =
                __floats2half2_rn(fmaxf(acc1[mf][nt][0], 0.f), fmaxf(acc1[mf][nt][1], 0.f));
            *(__half2*)(XB + ((row + 8) * XS + col) * 2) =
                __floats2half2_rn(fmaxf(acc1[mf][nt][2], 0.f), fmaxf(acc1[mf][nt][3], 0.f));
            *(__half2*)(XB + (row * XS + col + 128) * 2) =
                __floats2half2_rn(fmaxf(acc2[mf][nt][0], 0.f), fmaxf(acc2[mf][nt][1], 0.f));
            *(__half2*)(XB + ((row + 8) * XS + col + 128) * 2) =
                __floats2half2_rn(fmaxf(acc2[mf][nt][2], 0.f), fmaxf(acc2[mf][nt][3], 0.f));
        }
    }
    __syncthreads();
    // G2: h1 @ W2' -> acc2 = h pre-bias (fp32, kept in regs)
    gemm_tile<256>(aXB, g_FG2, acc2, lane, mg, ng);
    __syncthreads();

    // epilogue2: h = relu(acc2 + b2); keep fp32 in acc2, write fp16 XB cols 0-127
    #pragma unroll
    for (int mf = 0; mf < 2; mf++) {
        int row = mg * 32 + mf * 16 + (lane >> 2);
        #pragma unroll
        for (int nt = 0; nt < 4; nt++) {
            int col = ng * 32 + nt * 8 + (lane & 3) * 2;
            float v0 = fmaxf(acc2[mf][nt][0] + b2s[col],     0.f);
            float v1 = fmaxf(acc2[mf][nt][1] + b2s[col + 1], 0.f);
            float v2 = fmaxf(acc2[mf][nt][2] + b2s[col],     0.f);
            float v3 = fmaxf(acc2[mf][nt][3] + b2s[col + 1], 0.f);
            acc2[mf][nt][0] = v0; acc2[mf][nt][1] = v1;
            acc2[mf][nt][2] = v2; acc2[mf][nt][3] = v3;
            *(__half2*)(XB + (row * XS + col) * 2)       = __floats2half2_rn(v0, v1);
            *(__half2*)(XB + ((row + 8) * XS + col) * 2) = __floats2half2_rn(v2, v3);
        }
    }
    __syncthreads();
    // G3: h @ A1top -> acc1
    gemm_tile<128>(aXB, g_FG3, acc1, lane, mg, ng);

    // epilogue3: a1 = relu(acc1 + selfA1[node]) -> fp16 XB cols 128-255 (disjoint from G3 reads)
    {
        int node = mg >> 1;
        #pragma unroll
        for (int mf = 0; mf < 2; mf++) {
            int row = mg * 32 + mf * 16 + (lane >> 2);
            #pragma unroll
            for (int nt = 0; nt < 4; nt++) {
                int col = ng * 32 + nt * 8 + (lane & 3) * 2;
                float s0 = SA[node * 128 + col], s1 = SA[node * 128 + col + 1];
                *(__half2*)(XB + (row * XS + col + 128) * 2) =
                    __floats2half2_rn(fmaxf(acc1[mf][nt][0] + s0, 0.f),
                                      fmaxf(acc1[mf][nt][1] + s1, 0.f));
                *(__half2*)(XB + ((row + 8) * XS + col + 128) * 2) =
                    __floats2half2_rn(fmaxf(acc1[mf][nt][2] + s0, 0.f),
                                      fmaxf(acc1[mf][nt][3] + s1, 0.f));
            }
        }
    }
    __syncthreads();
    // G4: a1 @ A2 -> acc1
    gemm_tile<128>(aXB + 256, g_FG4, acc1, lane, mg, ng);

    // epilogue4: a2 = relu(acc1 + ab2); logit partials
    {
        float lp[4] = {0.f, 0.f, 0.f, 0.f};
        #pragma unroll
        for (int mf = 0; mf < 2; mf++)
            #pragma unroll
            for (int nt = 0; nt < 4; nt++) {
                int col = ng * 32 + nt * 8 + (lane & 3) * 2;
                float a30 = A3s[col], a31 = A3s[col + 1];
                float c0 = ab2s[col], c1 = ab2s[col + 1];
                lp[mf * 2 + 0] += fmaxf(acc1[mf][nt][0] + c0, 0.f) * a30
                                + fmaxf(acc1[mf][nt][1] + c1, 0.f) * a31;
                lp[mf * 2 + 1] += fmaxf(acc1[mf][nt][2] + c0, 0.f) * a30
                                + fmaxf(acc1[mf][nt][3] + c1, 0.f) * a31;
            }
        #pragma unroll
        for (int j = 0; j < 4; j++) {
            lp[j] += __shfl_xor_sync(0xffffffffu, lp[j], 1);
            lp[j] += __shfl_xor_sync(0xffffffffu, lp[j], 2);
        }
        if ((lane & 3) == 0) {
            int rbase = mg * 32 + (lane >> 2);
            #pragma unroll
            for (int j = 0; j < 4; j++)
                LGP[ng * 128 + rbase + j * 8] = lp[j];
        }
    }
    __syncthreads();
    if (tid < 128)
        LG[tid] = LGP[tid] + LGP[128 + tid] + LGP[256 + tid] + LGP[384 + tid]
                + *(float*)(sm + OFF_AB3);
    __syncthreads();
    if (wid < 2) {   // softmax per node over its 64 logits
        float a = LG[wid * 64 + lane], b = LG[wid * 64 + 32 + lane];
        float m = fmaxf(a, b);
        #pragma unroll
        for (int o = 16; o; o >>= 1) m = fmaxf(m, __shfl_xor_sync(0xffffffffu, m, o));
        float e1 = __expf(a - m), e2 = __expf(b - m), s = e1 + e2;
        #pragma unroll
        for (int o = 16; o; o >>= 1) s += __shfl_xor_sync(0xffffffffu, s, o);
        wgs[wid * 64 + lane] = e1 / s; wgs[wid * 64 + 32 + lane] = e2 / s;
    }
    __syncthreads();

    // weighted reduce: out[node][col] = sum_r wgs[r] * h[r][col]  (h fp32 in acc2)
    {
        float p[8];
        #pragma unroll
        for (int i = 0; i < 8; i++) p[i] = 0.f;
        #pragma unroll
        for (int mf = 0; mf < 2; mf++) {
            int r0 = mg * 32 + mf * 16 + (lane >> 2);
            float w0 = wgs[r0], w1 = wgs[r0 + 8];
            #pragma unroll
            for (int nt = 0; nt < 4; nt++) {
                p[nt * 2 + 0] += w0 * acc2[mf][nt][0] + w1 * acc2[mf][nt][2];
                p[nt * 2 + 1] += w0 * acc2[mf][nt][1] + w1 * acc2[mf][nt][3];
            }
        }
        #pragma unroll
        for (int i = 0; i < 8; i++) {
            p[i] += __shfl_xor_sync(0xffffffffu, p[i], 4);
            p[i] += __shfl_xor_sync(0xffffffffu, p[i], 8);
            p[i] += __shfl_xor_sync(0xffffffffu, p[i], 16);
        }
        if (lane < 4) {
            int node = mg >> 1;
            #pragma unroll
            for (int i = 0; i < 8; i++) {
                int col = ng * 32 + (i >> 1) * 8 + lane * 2 + (i & 1);
                atomicAdd(&OUTa[node * 128 + col], p[i]);
            }
        }
    }
    __syncthreads();
    if (tid < 256) out[(size_t)tile * 256 + tid] = OUTa[tid];
}

// ================= launch =================
extern "C" void kernel_launch(void* const* d_in, const int* in_sizes, int n_in,
                              void* d_out, int out_size) {
    const int*   nodes = (const int*)  d_in[0];
    const int*   prel  = (const int*)  d_in[1];
    const int*   pnbr  = (const int*)  d_in[2];
    const int*   attrs = (const int*)  d_in[3];
    const float* u2e   = (const float*)d_in[4];
    const float* r2e   = (const float*)d_in[5];
    const float* ua2e  = (const float*)d_in[6];
    const float* W1    = (const float*)d_in[7];
    const float* b1    = (const float*)d_in[8];
    const float* W2    = (const float*)d_in[9];
    const float* b2    = (const float*)d_in[10];
    const float* A1    = (const float*)d_in[11];
    const float* ab1   = (const float*)d_in[12];
    const float* A2    = (const float*)d_in[13];
    const float* ab2   = (const float*)d_in[14];
    const float* A3    = (const float*)d_in[15];
    const float* ab3   = (const float*)d_in[16];
    float* out = (float*)d_out;

    cudaFuncSetAttribute(k_selfA1, cudaFuncAttributeMaxDynamicSharedMemorySize, 65536);
    cudaFuncSetAttribute(k_main,   cudaFuncAttributeMaxDynamicSharedMemorySize, (int)SMEM_BYTES);

    k_convert<<<512, 256>>>(u2e, ua2e);
    k_r12<<<64, 256>>>(r2e, W1, b1);
    k_selfA1<<<512, 128, 65536>>>(nodes, u2e, A1, ab1);
    k_pack<<<144, 256>>>(W1, W2, A1, A2);
    k_main<<<2048, 512, SMEM_BYTES>>>(prel, pnbr, attrs, b2, ab2, A3, ab3, out);
}

// round 6
// speedup vs baseline: 1.5011x; 1.0838x over previous
#include <cuda_runtime.h>
#include <cuda_fp16.h>
#include <stdint.h>
#include <math.h>

#define DEVFN __device__ __forceinline__

static constexpr int NNODE = 4096, DIM = 128;
static constexpr int NU = 100000, NR = 32, NA = 5000;

// ---- device scratch (no allocs allowed) ----
__device__ __align__(16) __half g_u2e_h [NU * DIM];
__device__ __align__(16) __half g_ua2e_h[NA * DIM];
__device__ __align__(16) float  g_R12T  [2 * NR * 256];
__device__ __align__(16) float  g_selfA1[NNODE * DIM];
// B operands in MMA-fragment order: uint2(b0,b1) indexed [ks][nb][lane]
__device__ __align__(16) uint2  g_FG1[2 * 20 * 16 * 32];  // G1 two n-halves, K=320
__device__ __align__(16) uint2  g_FG2[16 * 16 * 32];      // G2 K=256
__device__ __align__(16) uint2  g_FG3[8 * 16 * 32];       // G3 K=128
__device__ __align__(16) uint2  g_FG4[8 * 16 * 32];       // G4 K=128

// ---- smem layout (bytes) ----
static constexpr uint32_t OFF_B2S = 0, OFF_AB2 = 512, OFF_A3 = 1024, OFF_SA = 1536,
    OFF_LG = 2560, OFF_LGP = 3072, OFF_WGT = 5120, OFF_OUT = 5632, OFF_AB3 = 6656,
    OFF_XB = 6912;
static constexpr int XS = 328;                        // X stride (halfs)
static constexpr uint32_t SMEM_BYTES = OFF_XB + 128 * XS * 2;   // 90880

// ---- PTX helpers ----
DEVFN uint32_t smem_u32(const void* p) {
    uint32_t a;
    asm("{ .reg .u64 t; cvta.to.shared.u64 t, %1; cvt.u32.u64 %0, t; }" : "=r"(a) : "l"(p));
    return a;
}
DEVFN void ldm4(uint32_t* r, uint32_t a) {
    asm volatile("ldmatrix.sync.aligned.m8n8.x4.shared.b16 {%0,%1,%2,%3}, [%4];"
                 : "=r"(r[0]), "=r"(r[1]), "=r"(r[2]), "=r"(r[3]) : "r"(a));
}
DEVFN void mma16816(float* c, const uint32_t* a, uint32_t b0, uint32_t b1) {
    asm volatile("mma.sync.aligned.m16n8k16.row.col.f32.f16.f16.f32 "
                 "{%0,%1,%2,%3}, {%4,%5,%6,%7}, {%8,%9}, {%0,%1,%2,%3};"
                 : "+f"(c[0]), "+f"(c[1]), "+f"(c[2]), "+f"(c[3])
                 : "r"(a[0]), "r"(a[1]), "r"(a[2]), "r"(a[3]), "r"(b0), "r"(b1));
}

// single GEMM with register double-buffered B prefetch
template<int K>
DEVFN void gemm_tile(uint32_t aXbase, const uint2* __restrict__ F,
                     float (&acc)[2][4][4], int lane, int mg, int ng) {
    constexpr int KS = K / 16;
    uint32_t aA = aXbase + (uint32_t)((mg * 32 + ((lane >> 3) & 1) * 8 + (lane & 7)) * XS
                                      + (lane >> 4) * 8) * 2;
    const uint2* Fw = F + (ng * 4) * 32 + lane;
    #pragma unroll
    for (int m = 0; m < 2; m++)
        #pragma unroll
        for (int n = 0; n < 4; n++)
            #pragma unroll
            for (int e = 0; e < 4; e++) acc[m][n][e] = 0.f;
    uint2 bf[4], bn[4];
    #pragma unroll
    for (int nt = 0; nt < 4; nt++) bf[nt] = __ldg(Fw + nt * 32);
    #pragma unroll 1
    for (int ks = 0; ks < KS; ks++) {
        if (ks + 1 < KS) {
            #pragma unroll
            for (int nt = 0; nt < 4; nt++) bn[nt] = __ldg(Fw + ((ks + 1) * 16 + nt) * 32);
        }
        uint32_t a0[4], a1[4];
        ldm4(a0, aA + ks * 32);
        ldm4(a1, aA + 16 * XS * 2 + ks * 32);
        #pragma unroll
        for (int nt = 0; nt < 4; nt++) {
            mma16816(acc[0][nt], a0, bf[nt].x, bf[nt].y);
            mma16816(acc[1][nt], a1, bf[nt].x, bf[nt].y);
        }
        #pragma unroll
        for (int nt = 0; nt < 4; nt++) bf[nt] = bn[nt];
    }
}

// dual GEMM (shared A fragments, two B tables / two accumulators), prefetched
template<int K>
DEVFN void gemm_dual(uint32_t aXbase, const uint2* __restrict__ F0,
                     const uint2* __restrict__ F1,
                     float (&acc1)[2][4][4], float (&acc2)[2][4][4],
                     int lane, int mg, int ng) {
    constexpr int KS = K / 16;
    uint32_t aA = aXbase + (uint32_t)((mg * 32 + ((lane >> 3) & 1) * 8 + (lane & 7)) * XS
                                      + (lane >> 4) * 8) * 2;
    const uint2* Fw0 = F0 + (ng * 4) * 32 + lane;
    const uint2* Fw1 = F1 + (ng * 4) * 32 + lane;
    #pragma unroll
    for (int m = 0; m < 2; m++)
        #pragma unroll
        for (int n = 0; n < 4; n++)
            #pragma unroll
            for (int e = 0; e < 4; e++) { acc1[m][n][e] = 0.f; acc2[m][n][e] = 0.f; }
    uint2 bf0[4], bf1[4], bn0[4], bn1[4];
    #pragma unroll
    for (int nt = 0; nt < 4; nt++) { bf0[nt] = __ldg(Fw0 + nt * 32); bf1[nt] = __ldg(Fw1 + nt * 32); }
    #pragma unroll 1
    for (int ks = 0; ks < KS; ks++) {
        if (ks + 1 < KS) {
            #pragma unroll
            for (int nt = 0; nt < 4; nt++) {
                bn0[nt] = __ldg(Fw0 + ((ks + 1) * 16 + nt) * 32);
                bn1[nt] = __ldg(Fw1 + ((ks + 1) * 16 + nt) * 32);
            }
        }
        uint32_t a0[4], a1[4];
        ldm4(a0, aA + ks * 32);
        ldm4(a1, aA + 16 * XS * 2 + ks * 32);
        #pragma unroll
        for (int nt = 0; nt < 4; nt++) {
            mma16816(acc1[0][nt], a0, bf0[nt].x, bf0[nt].y);
            mma16816(acc1[1][nt], a1, bf0[nt].x, bf0[nt].y);
            mma16816(acc2[0][nt], a0, bf1[nt].x, bf1[nt].y);
            mma16816(acc2[1][nt], a1, bf1[nt].x, bf1[nt].y);
        }
        #pragma unroll
        for (int nt = 0; nt < 4; nt++) { bf0[nt] = bn0[nt]; bf1[nt] = bn1[nt]; }
    }
}

// ================= prepass 1: convert || r12 || selfA1 =================
__global__ void k_prep1(const float* __restrict__ u2e, const float* __restrict__ ua2e,
                        const float* __restrict__ r2e, const float* __restrict__ W1,
                        const float* __restrict__ b1, const int* __restrict__ nodes,
                        const float* __restrict__ A1, const float* __restrict__ ab1) {
    extern __shared__ float sh[];
    int b = blockIdx.x, tid = threadIdx.x;
    if (b < 512) {
        int st = 512 * 256, t0 = b * 256 + tid;
        const float4* s1 = (const float4*)u2e;  __half2* d1 = (__half2*)g_u2e_h;
        for (int i = t0; i < NU * DIM / 4; i += st) {
            float4 v = s1[i];
            d1[2 * i] = __floats2half2_rn(v.x, v.y); d1[2 * i + 1] = __floats2half2_rn(v.z, v.w);
        }
        const float4* s2 = (const float4*)ua2e;  __half2* d2 = (__half2*)g_ua2e_h;
        for (int i = t0; i < NA * DIM / 4; i += st) {
            float4 v = s2[i];
            d2[2 * i] = __floats2half2_rn(v.x, v.y); d2[2 * i + 1] = __floats2half2_rn(v.z, v.w);
        }
    } else if (b < 576) {
        float* rr = sh;
        int bb = b - 512, t = bb >> 5, i = bb & 31, c = tid;
        if (c < 128) rr[c] = r2e[i * 128 + c];
        __syncthreads();
        float acc = (t == 0) ? b1[c] : 0.f;
        #pragma unroll 4
        for (int k = 0; k < 128; k++) acc += rr[k] * W1[(t * 128 + k) * 256 + c];
        g_R12T[(t * 32 + i) * 256 + c] = acc;
    } else {
        float* As  = sh;            // [128][128] A1 bottom
        float* se  = sh + 16384;
        float* par = sh + 16384 + 128;
        int bb = b - 576;
        for (int i = tid; i < 16384; i += 256) As[i] = A1[16384 + i];
        __syncthreads();
        int col = tid & 127, kh = tid >> 7;
        for (int s = 0; s < 8; s++) {
            int n = bb * 8 + s, nd = nodes[n];
            if (tid < 128) se[tid] = u2e[(size_t)nd * 128 + tid];
            __syncthreads();
            float acc = 0.f;
            #pragma unroll 8
            for (int k = kh * 64; k < kh * 64 + 64; k++) acc += se[k] * As[k * 128 + col];
            par[tid] = acc;
            __syncthreads();
            if (tid < 128) g_selfA1[n * 128 + tid] = par[tid] + par[tid + 128] + ab1[tid];
            __syncthreads();
        }
    }
}

DEVFN uint32_t pack2(float a, float b) {
    __half2 h = __floats2half2_rn(a, b);
    return *(uint32_t*)&h;
}

// ================= prepass 2: pack B into MMA fragment order =================
__global__ void k_pack(const float* __restrict__ W1, const float* __restrict__ W2,
                       const float* __restrict__ A1, const float* __restrict__ A2) {
    int id = blockIdx.x * 256 + threadIdx.x;   // 144 x 256 = 36864
    int table, rem, h = 0;
    if (id < 20480)      { table = 1; h = id / 10240; rem = id % 10240; }
    else if (id < 28672) { table = 2; rem = id - 20480; }
    else if (id < 32768) { table = 3; rem = id - 28672; }
    else                 { table = 4; rem = id - 32768; }
    int lane = rem & 31, nb = (rem >> 5) & 15, ks = rem >> 9;
    int n = nb * 8 + (lane >> 2), k0 = ks * 16 + (lane & 3) * 2;

    float v[4];
    #pragma unroll
    for (int j = 0; j < 4; j++) {
        int k = k0 + (j >> 1) * 8 + (j & 1);
        float val;
        if (table == 1) {
            int ngl = h * 128 + n;
            if (k < 256)      val = W1[(256 + k) * 256 + ngl];
            else if (k < 288) val = g_R12T[(k - 256) * 256 + ngl];
            else              val = g_R12T[(32 + (k - 288)) * 256 + ngl];
        } else if (table == 2) val = W2[k * 128 + n];
        else if (table == 3)   val = A1[k * 128 + n];
        else                   val = A2[k * 128 + n];
        v[j] = val;
    }
    uint2 fr = make_uint2(pack2(v[0], v[1]), pack2(v[2], v[3]));
    if (table == 1)      g_FG1[h * 10240 + rem] = fr;
    else if (table == 2) g_FG2[rem] = fr;
    else if (table == 3) g_FG3[rem] = fr;
    else                 g_FG4[rem] = fr;
}

// ================= main fused kernel =================
__global__ void __launch_bounds__(512, 1)
k_main(const int* __restrict__ prel, const int* __restrict__ pnbr,
       const int* __restrict__ attrs,
       const float* __restrict__ b2, const float* __restrict__ ab2,
       const float* __restrict__ A3, const float* __restrict__ ab3,
       float* __restrict__ out) {
    extern __shared__ char sm[];
    const uint32_t sb = smem_u32(sm);
    const int tid = threadIdx.x, wid = tid >> 5, lane = tid & 31;
    const int mg = wid >> 2, ng = wid & 3;
    const int tile = blockIdx.x;

    float* b2s  = (float*)(sm + OFF_B2S);
    float* ab2s = (float*)(sm + OFF_AB2);
    float* A3s  = (float*)(sm + OFF_A3);
    float* SA   = (float*)(sm + OFF_SA);
    float* LG   = (float*)(sm + OFF_LG);
    float* LGP  = (float*)(sm + OFF_LGP);
    float* wgs  = (float*)(sm + OFF_WGT);
    float* OUTa = (float*)(sm + OFF_OUT);
    char*  XB   = sm + OFF_XB;
    const uint32_t aXB = sb + OFF_XB;

    if (tid < 128) { b2s[tid] = b2[tid]; ab2s[tid] = ab2[tid]; A3s[tid] = A3[tid]; }
    if (tid == 0) *(float*)(sm + OFF_AB3) = ab3[0];
    if (tid < 256) { SA[tid] = g_selfA1[(size_t)tile * 256 + tid]; OUTa[tid] = 0.f; }

    // ---- build X = [ne(128) | ae(128) | onehot r0(32) | onehot r1(32)], 4 thr/row ----
    {
        int row = tid >> 2, q = tid & 3, p = tile * 128 + row;
        char* XR = XB + row * (XS * 2);
        int nbr = pnbr[p];
        const uint4* s = (const uint4*)(g_u2e_h + (size_t)nbr * 128 + q * 32);
        #pragma unroll
        for (int j = 0; j < 4; j++) ((uint4*)XR)[q * 4 + j] = s[j];
        if (q == 0) {
            #pragma unroll
            for (int j = 0; j < 8; j++) ((uint4*)(XR + 512))[j] = make_uint4(0, 0, 0, 0);
        }
        int at[8];
        const int4* ap = (const int4*)(attrs + (size_t)p * 8);
        int4 a0v = ap[0], a1v = ap[1];
        at[0]=a0v.x; at[1]=a0v.y; at[2]=a0v.z; at[3]=a0v.w;
        at[4]=a1v.x; at[5]=a1v.y; at[6]=a1v.z; at[7]=a1v.w;
        float2 acc[16];
        #pragma unroll
        for (int i = 0; i < 16; i++) { acc[i].x = 0.f; acc[i].y = 0.f; }
        #pragma unroll 1
        for (int a = 0; a < 8; a++) {
            const __half2* qp = (const __half2*)(g_ua2e_h + (size_t)at[a] * 128 + q * 32);
            #pragma unroll
            for (int i = 0; i < 16; i++) {
                float2 f = __half22float2(qp[i]);
                acc[i].x += f.x; acc[i].y += f.y;
            }
        }
        #pragma unroll
        for (int i = 0; i < 16; i++)
            *(__half2*)(XR + (128 + q * 32 + 2 * i) * 2) = __floats2half2_rn(acc[i].x, acc[i].y);
        if (q == 0) {
            int r0 = prel[p * 2], r1 = prel[p * 2 + 1];
            *(__half*)(XR + (256 + r0) * 2) = __ushort_as_half((unsigned short)0x3C00);
            *(__half*)(XR + (288 + r1) * 2) = __ushort_as_half((unsigned short)0x3C00);
        }
    }
    __syncthreads();

    float acc1[2][4][4], acc2[2][4][4];

    // G1 (dual): X @ W1' -> h1 cols 0-127 (acc1), 128-255 (acc2)
    gemm_dual<320>(aXB, g_FG1, g_FG1 + 10240, acc1, acc2, lane, mg, ng);
    __syncthreads();

    // epilogue1: h1 = relu -> fp16 XB cols 0-255 (overwrites X)
    #pragma unroll
    for (int mf = 0; mf < 2; mf++) {
        int row = mg * 32 + mf * 16 + (lane >> 2);
        #pragma unroll
        for (int nt = 0; nt < 4; nt++) {
            int col = ng * 32 + nt * 8 + (lane & 3) * 2;
            *(__half2*)(XB + (row * XS + col) * 2) =
                __floats2half2_rn(fmaxf(acc1[mf][nt][0], 0.f), fmaxf(acc1[mf][nt][1], 0.f));
            *(__half2*)(XB + ((row + 8) * XS + col) * 2) =
                __floats2half2_rn(fmaxf(acc1[mf][nt][2], 0.f), fmaxf(acc1[mf][nt][3], 0.f));
            *(__half2*)(XB + (row * XS + col + 128) * 2) =
                __floats2half2_rn(fmaxf(acc2[mf][nt][0], 0.f), fmaxf(acc2[mf][nt][1], 0.f));
            *(__half2*)(XB + ((row + 8) * XS + col + 128) * 2) =
                __floats2half2_rn(fmaxf(acc2[mf][nt][2], 0.f), fmaxf(acc2[mf][nt][3], 0.f));
        }
    }
    __syncthreads();
    // G2: h1 @ W2' -> acc2 = h pre-bias (fp32, kept in regs)
    gemm_tile<256>(aXB, g_FG2, acc2, lane, mg, ng);
    __syncthreads();

    // epilogue2: h = relu(acc2 + b2); keep fp32 in acc2, write fp16 XB cols 0-127
    #pragma unroll
    for (int mf = 0; mf < 2; mf++) {
        int row = mg * 32 + mf * 16 + (lane >> 2);
        #pragma unroll
        for (int nt = 0; nt < 4; nt++) {
            int col = ng * 32 + nt * 8 + (lane & 3) * 2;
            float v0 = fmaxf(acc2[mf][nt][0] + b2s[col],     0.f);
            float v1 = fmaxf(acc2[mf][nt][1] + b2s[col + 1], 0.f);
            float v2 = fmaxf(acc2[mf][nt][2] + b2s[col],     0.f);
            float v3 = fmaxf(acc2[mf][nt][3] + b2s[col + 1], 0.f);
            acc2[mf][nt][0] = v0; acc2[mf][nt][1] = v1;
            acc2[mf][nt][2] = v2; acc2[mf][nt][3] = v3;
            *(__half2*)(XB + (row * XS + col) * 2)       = __floats2half2_rn(v0, v1);
            *(__half2*)(XB + ((row + 8) * XS + col) * 2) = __floats2half2_rn(v2, v3);
        }
    }
    __syncthreads();
    // G3: h @ A1top -> acc1
    gemm_tile<128>(aXB, g_FG3, acc1, lane, mg, ng);

    // epilogue3: a1 = relu(acc1 + selfA1[node]) -> fp16 XB cols 128-255
    {
        int node = mg >> 1;
        #pragma unroll
        for (int mf = 0; mf < 2; mf++) {
            int row = mg * 32 + mf * 16 + (lane >> 2);
            #pragma unroll
            for (int nt = 0; nt < 4; nt++) {
                int col = ng * 32 + nt * 8 + (lane & 3) * 2;
                float s0 = SA[node * 128 + col], s1 = SA[node * 128 + col + 1];
                *(__half2*)(XB + (row * XS + col + 128) * 2) =
                    __floats2half2_rn(fmaxf(acc1[mf][nt][0] + s0, 0.f),
                                      fmaxf(acc1[mf][nt][1] + s1, 0.f));
                *(__half2*)(XB + ((row + 8) * XS + col + 128) * 2) =
                    __floats2half2_rn(fmaxf(acc1[mf][nt][2] + s0, 0.f),
                                      fmaxf(acc1[mf][nt][3] + s1, 0.f));
            }
        }
    }
    __syncthreads();
    // G4: a1 @ A2 -> acc1
    gemm_tile<128>(aXB + 256, g_FG4, acc1, lane, mg, ng);

    // epilogue4: a2 = relu(acc1 + ab2); logit partials
    {
        float lp[4] = {0.f, 0.f, 0.f, 0.f};
        #pragma unroll
        for (int mf = 0; mf < 2; mf++)
            #pragma unroll
            for (int nt = 0; nt < 4; nt++) {
                int col = ng * 32 + nt * 8 + (lane & 3) * 2;
                float a30 = A3s[col], a31 = A3s[col + 1];
                float c0 = ab2s[col], c1 = ab2s[col + 1];
                lp[mf * 2 + 0] += fmaxf(acc1[mf][nt][0] + c0, 0.f) * a30
                                + fmaxf(acc1[mf][nt][1] + c1, 0.f) * a31;
                lp[mf * 2 + 1] += fmaxf(acc1[mf][nt][2] + c0, 0.f) * a30
                                + fmaxf(acc1[mf][nt][3] + c1, 0.f) * a31;
            }
        #pragma unroll
        for (int j = 0; j < 4; j++) {
            lp[j] += __shfl_xor_sync(0xffffffffu, lp[j], 1);
            lp[j] += __shfl_xor_sync(0xffffffffu, lp[j], 2);
        }
        if ((lane & 3) == 0) {
            int rbase = mg * 32 + (lane >> 2);
            #pragma unroll
            for (int j = 0; j < 4; j++)
                LGP[ng * 128 + rbase + j * 8] = lp[j];
        }
    }
    __syncthreads();
    if (tid < 128)
        LG[tid] = LGP[tid] + LGP[128 + tid] + LGP[256 + tid] + LGP[384 + tid]
                + *(float*)(sm + OFF_AB3);
    __syncthreads();
    if (wid < 2) {   // softmax per node over its 64 logits
        float a = LG[wid * 64 + lane], b = LG[wid * 64 + 32 + lane];
        float m = fmaxf(a, b);
        #pragma unroll
        for (int o = 16; o; o >>= 1) m = fmaxf(m, __shfl_xor_sync(0xffffffffu, m, o));
        float e1 = __expf(a - m), e2 = __expf(b - m), s = e1 + e2;
        #pragma unroll
        for (int o = 16; o; o >>= 1) s += __shfl_xor_sync(0xffffffffu, s, o);
        wgs[wid * 64 + lane] = e1 / s; wgs[wid * 64 + 32 + lane] = e2 / s;
    }
    __syncthreads();

    // weighted reduce: out[node][col] = sum_r wgs[r] * h[r][col]  (h fp32 in acc2)
    {
        float p[8];
        #pragma unroll
        for (int i = 0; i < 8; i++) p[i] = 0.f;
        #pragma unroll
        for (int mf = 0; mf < 2; mf++) {
            int r0 = mg * 32 + mf * 16 + (lane >> 2);
            float w0 = wgs[r0], w1 = wgs[r0 + 8];
            #pragma unroll
            for (int nt = 0; nt < 4; nt++) {
                p[nt * 2 + 0] += w0 * acc2[mf][nt][0] + w1 * acc2[mf][nt][2];
                p[nt * 2 + 1] += w0 * acc2[mf][nt][1] + w1 * acc2[mf][nt][3];
            }
        }
        #pragma unroll
        for (int i = 0; i < 8; i++) {
            p[i] += __shfl_xor_sync(0xffffffffu, p[i], 4);
            p[i] += __shfl_xor_sync(0xffffffffu, p[i], 8);
            p[i] += __shfl_xor_sync(0xffffffffu, p[i], 16);
        }
        if (lane < 4) {
            int node = mg >> 1;
            #pragma unroll
            for (int i = 0; i < 8; i++) {
                int col = ng * 32 + (i >> 1) * 8 + lane * 2 + (i & 1);
                atomicAdd(&OUTa[node * 128 + col], p[i]);
            }
        }
    }
    __syncthreads();
    if (tid < 256) out[(size_t)tile * 256 + tid] = OUTa[tid];
}

// ================= launch =================
extern "C" void kernel_launch(void* const* d_in, const int* in_sizes, int n_in,
                              void* d_out, int out_size) {
    const int*   nodes = (const int*)  d_in[0];
    const int*   prel  = (const int*)  d_in[1];
    const int*   pnbr  = (const int*)  d_in[2];
    const int*   attrs = (const int*)  d_in[3];
    const float* u2e   = (const float*)d_in[4];
    const float* r2e   = (const float*)d_in[5];
    const float* ua2e  = (const float*)d_in[6];
    const float* W1    = (const float*)d_in[7];
    const float* b1    = (const float*)d_in[8];
    const float* W2    = (const float*)d_in[9];
    const float* b2    = (const float*)d_in[10];
    const float* A1    = (const float*)d_in[11];
    const float* ab1   = (const float*)d_in[12];
    const float* A2    = (const float*)d_in[13];
    const float* ab2   = (const float*)d_in[14];
    const float* A3    = (const float*)d_in[15];
    const float* ab3   = (const float*)d_in[16];
    float* out = (float*)d_out;

    const int prep1_smem = (16384 + 128 + 256) * 4;   // 67072
    cudaFuncSetAttribute(k_prep1, cudaFuncAttributeMaxDynamicSharedMemorySize, prep1_smem);
    cudaFuncSetAttribute(k_main,  cudaFuncAttributeMaxDynamicSharedMemorySize, (int)SMEM_BYTES);

    k_prep1<<<1088, 256, prep1_smem>>>(u2e, ua2e, r2e, W1, b1, nodes, A1, ab1);
    k_pack<<<144, 256>>>(W1, W2, A1, A2);
    k_main<<<2048, 512, SMEM_BYTES>>>(prel, pnbr, attrs, b2, ab2, A3, ab3, out);
}